// round 17
// baseline (speedup 1.0000x reference)
#include <cuda_runtime.h>
#include <cstdint>
#include <cstddef>

// Problem dims
#define NH    8
#define NSEQ  4096
#define FIN   512
#define HD    64
#define FOUT  512

#define QT 128          // query rows per CTA (8 warps x 16)
#define KT 64           // keys per iteration
#define NIT (NSEQ / KT)

// Scratch (device globals: allocation-free rule)
__device__ float g_Q[NH * NSEQ * HD];   // tf32, pre-scaled by 1/8
__device__ float g_K[NH * NSEQ * HD];   // tf32
__device__ float g_V[NH * NSEQ * HD];   // tf32
__device__ float g_C[NSEQ * NH * HD];   // [n][h*HD+d], tf32-rounded

__device__ __forceinline__ float to_tf32(float x) {
    float r; asm("cvt.rna.tf32.f32 %0, %1;" : "=f"(r) : "f"(x)); return r;
}

// m16n8k8 tf32 MMA
__device__ __forceinline__ void mma8(float* c, const uint32_t* a, uint32_t b0, uint32_t b1) {
    asm volatile(
        "mma.sync.aligned.m16n8k8.row.col.f32.tf32.tf32.f32 "
        "{%0,%1,%2,%3}, {%4,%5,%6,%7}, {%8,%9}, {%0,%1,%2,%3};"
        : "+f"(c[0]), "+f"(c[1]), "+f"(c[2]), "+f"(c[3])
        : "r"(a[0]), "r"(a[1]), "r"(a[2]), "r"(a[3]), "r"(b0), "r"(b1));
}

__device__ __forceinline__ uint32_t smem_u32(const void* p) {
    uint32_t a;
    asm("{ .reg .u64 t; cvta.to.shared.u64 t, %1; cvt.u32.u64 %0, t; }" : "=r"(a) : "l"(p));
    return a;
}
__device__ __forceinline__ void cp16(uint32_t dst, const float* src) {
    asm volatile("cp.async.cg.shared.global [%0], [%1], 16;"
                 :: "r"(dst), "l"(__cvta_generic_to_global(src)));
}
#define CP_COMMIT() asm volatile("cp.async.commit_group;" ::: "memory")
#define CP_WAIT(N)  asm volatile("cp.async.wait_group " #N ";" ::: "memory")

// ---------------------------------------------------------------------------
// Dummies: keep attn at ncu capture index 5.
// ---------------------------------------------------------------------------
__global__ void dummy_kernel() {}

// ---------------------------------------------------------------------------
// Kernel 1: QKV projection via mma.sync tf32 (R12 version, measured ~76us).
// grid = (NSEQ/128, NH, 3), block = 256.
// ---------------------------------------------------------------------------
__global__ __launch_bounds__(256, 3) void qkv_kernel(
    const float* __restrict__ X,
    const float* __restrict__ Wq,
    const float* __restrict__ Wk,
    const float* __restrict__ Wv)
{
    __shared__ float Xs[128][36];
    __shared__ float Ws[64][36];

    const int h  = blockIdx.y;
    const int m0 = blockIdx.x * 128;
    const int z  = blockIdx.z;
    const float* W = (z == 0) ? Wq : (z == 1) ? Wk : Wv;
    float* Out     = (z == 0) ? g_Q : (z == 1) ? g_K : g_V;
    const float sc = (z == 0) ? 0.125f : 1.0f;

    const int tid  = threadIdx.x;
    const int wid  = tid >> 5;
    const int lane = tid & 31;
    const int g = lane >> 2;
    const int t = lane & 3;
    const int wrow = wid * 16;

    const float* Xh = X + (size_t)h * NSEQ * FIN;
    const float* Wh = W + (size_t)h * HD * FIN;

    float acc[8][4];
    #pragma unroll
    for (int nb = 0; nb < 8; nb++)
        #pragma unroll
        for (int i = 0; i < 4; i++) acc[nb][i] = 0.f;

    for (int f0 = 0; f0 < FIN; f0 += 32) {
        #pragma unroll
        for (int u = 0; u < 4; u++) {
            int idx = tid + u * 256;
            int r = idx >> 3, c4 = (idx & 7) << 2;
            float4 v = *(const float4*)(Xh + (size_t)(m0 + r) * FIN + f0 + c4);
            Xs[r][c4 + 0] = to_tf32(v.x); Xs[r][c4 + 1] = to_tf32(v.y);
            Xs[r][c4 + 2] = to_tf32(v.z); Xs[r][c4 + 3] = to_tf32(v.w);
        }
        #pragma unroll
        for (int u = 0; u < 2; u++) {
            int idx = tid + u * 256;
            int r = idx >> 3, c4 = (idx & 7) << 2;
            float4 v = *(const float4*)(Wh + (size_t)r * FIN + f0 + c4);
            Ws[r][c4 + 0] = to_tf32(v.x); Ws[r][c4 + 1] = to_tf32(v.y);
            Ws[r][c4 + 2] = to_tf32(v.z); Ws[r][c4 + 3] = to_tf32(v.w);
        }
        __syncthreads();

        uint32_t a[4][4];
        #pragma unroll
        for (int ks = 0; ks < 4; ks++) {
            const float* Xr = &Xs[wrow + g][ks * 8 + t];
            a[ks][0] = __float_as_uint(Xr[0]);
            a[ks][1] = __float_as_uint(Xr[8 * 36]);
            a[ks][2] = __float_as_uint(Xr[4]);
            a[ks][3] = __float_as_uint(Xr[8 * 36 + 4]);
        }
        #pragma unroll
        for (int nb = 0; nb < 8; nb++) {
            #pragma unroll
            for (int ks = 0; ks < 4; ks++) {
                const float* Wp = &Ws[nb * 8 + g][ks * 8 + t];
                mma8(acc[nb], a[ks], __float_as_uint(Wp[0]), __float_as_uint(Wp[4]));
            }
        }
        __syncthreads();
    }

    #pragma unroll
    for (int nb = 0; nb < 8; nb++) {
        size_t r0 = ((size_t)h * NSEQ + m0 + wrow + g) * HD + nb * 8 + 2 * t;
        float2 v0 = make_float2(to_tf32(acc[nb][0] * sc), to_tf32(acc[nb][1] * sc));
        float2 v1 = make_float2(to_tf32(acc[nb][2] * sc), to_tf32(acc[nb][3] * sc));
        *(float2*)(Out + r0) = v0;
        *(float2*)(Out + r0 + (size_t)8 * HD) = v1;
    }
}

// ---------------------------------------------------------------------------
// Kernel 2: flash attention v2.
//  - Q persistent in SMEM (A-fragments on demand; qa registers freed)
//  - P via shfl (no P SMEM region, no staging round-trip)
//  - 2-stage cp.async double-buffered K/V tiles (hides per-iter tile latency)
// grid = (NSEQ/128, NH), block = 256 (8 warps x 16 query rows).
// SMEM: Qs[128][68] | stage0 K,V[64][68] | stage1 K,V[64][68] = 104448 B.
// ---------------------------------------------------------------------------
#define KV_STRIDE 68
#define SM_STAGE  (2 * 64 * KV_STRIDE)     // floats per K+V stage (8704)
#define SM_ST0    (128 * KV_STRIDE)        // stages start after Qs (8704)
#define ATTN_SMEM_FLOATS (SM_ST0 + 2 * SM_STAGE)
#define ATTN_SMEM_BYTES  (ATTN_SMEM_FLOATS * 4)   // 104448

__global__ __launch_bounds__(256, 2) void attn_kernel(const int* __restrict__ mask)
{
    extern __shared__ float smf[];
    float* Qs = smf;

    const int tid  = threadIdx.x;
    const int wid  = tid >> 5;
    const int lane = tid & 31;
    const int g = lane >> 2;
    const int t = lane & 3;

    const int h  = blockIdx.y;
    const int q0 = blockIdx.x * QT;
    const int wrow = wid * 16;
    const uint32_t smb = smem_u32(smf);

    // ---- Stage Q tile (128x64) into persistent SMEM region ----
    {
        const float* Qg = g_Q + ((size_t)h * NSEQ + q0) * HD;
        for (int idx = tid; idx < 128 * 16; idx += 256) {
            int r = idx >> 4, c4 = (idx & 15) << 2;
            float4 v = *(const float4*)(Qg + (size_t)r * HD + c4);
            *(float4*)(Qs + r * KV_STRIDE + c4) = v;
        }
    }

    // ---- prefetch K/V tile 0 into stage 0 ----
    {
        const float* Kg = g_K + (size_t)h * NSEQ * HD;
        const float* Vg = g_V + (size_t)h * NSEQ * HD;
        uint32_t base = smb + (uint32_t)SM_ST0 * 4;
        #pragma unroll
        for (int u = 0; u < 4; u++) {
            int idx = tid + u * 256;
            int r = idx >> 4, c4 = (idx & 15) << 2;
            uint32_t off = (uint32_t)(r * KV_STRIDE + c4) * 4;
            cp16(base + off, Kg + (size_t)r * HD + c4);
            cp16(base + (uint32_t)(64 * KV_STRIDE * 4) + off, Vg + (size_t)r * HD + c4);
        }
        CP_COMMIT();
    }

    float oacc[8][4];
    #pragma unroll
    for (int nb = 0; nb < 8; nb++)
        #pragma unroll
        for (int i = 0; i < 4; i++) oacc[nb][i] = 0.f;

    float m_lo = -3.0e38f, m_hi = -3.0e38f;
    float l_lo = 0.f, l_hi = 0.f;

    const int* mrow_lo = mask + ((size_t)h * NSEQ + q0 + wrow + g) * NSEQ;
    const int* mrow_hi = mrow_lo + (size_t)8 * NSEQ;

    const int lane_lo = (lane & ~3) | (t >> 1);
    const int lane_hi = lane_lo + 2;
    const bool odd = (t & 1);

    for (int it = 0; it < NIT; it++) {
        const int k0 = it * KT;

        // prefetch next tile into the other stage, then wait for current
        if (it + 1 < NIT) {
            const float* Kg = g_K + ((size_t)h * NSEQ + (it + 1) * KT) * HD;
            const float* Vg = g_V + ((size_t)h * NSEQ + (it + 1) * KT) * HD;
            uint32_t base = smb + (uint32_t)(SM_ST0 + ((it + 1) & 1) * SM_STAGE) * 4;
            #pragma unroll
            for (int u = 0; u < 4; u++) {
                int idx = tid + u * 256;
                int r = idx >> 4, c4 = (idx & 15) << 2;
                uint32_t off = (uint32_t)(r * KV_STRIDE + c4) * 4;
                cp16(base + off, Kg + (size_t)r * HD + c4);
                cp16(base + (uint32_t)(64 * KV_STRIDE * 4) + off, Vg + (size_t)r * HD + c4);
            }
            CP_COMMIT();
            CP_WAIT(1);
        } else {
            CP_WAIT(0);
        }
        __syncthreads();   // current stage ready; also orders Q staging (iter 0)

        const float* Ks = smf + SM_ST0 + (it & 1) * SM_STAGE;
        const float* Vs = Ks + 64 * KV_STRIDE;

        // ---- S = Q @ K^T (A fragments loaded on demand from Qs) ----
        float sacc[8][4];
        #pragma unroll
        for (int nb = 0; nb < 8; nb++)
            #pragma unroll
            for (int i = 0; i < 4; i++) sacc[nb][i] = 0.f;

        #pragma unroll
        for (int ks = 0; ks < 8; ks++) {
            const float* Qr = Qs + (wrow + g) * KV_STRIDE + ks * 8 + t;
            uint32_t a[4];
            a[0] = __float_as_uint(Qr[0]);
            a[1] = __float_as_uint(Qr[8 * KV_STRIDE]);
            a[2] = __float_as_uint(Qr[4]);
            a[3] = __float_as_uint(Qr[8 * KV_STRIDE + 4]);
            #pragma unroll
            for (int nb = 0; nb < 8; nb++) {
                const float* Kp = Ks + (nb * 8 + g) * KV_STRIDE + ks * 8 + t;
                mma8(sacc[nb], a, __float_as_uint(Kp[0]), __float_as_uint(Kp[4]));
            }
        }

        // ---- mask + online softmax ----
        float mx_lo = -3.0e38f, mx_hi = -3.0e38f;
        #pragma unroll
        for (int nb = 0; nb < 8; nb++) {
            int2 ml = *(const int2*)(mrow_lo + k0 + nb * 8 + 2 * t);
            int2 mh = *(const int2*)(mrow_hi + k0 + nb * 8 + 2 * t);
            sacc[nb][0] = ml.x ? sacc[nb][0] : -1e30f;
            sacc[nb][1] = ml.y ? sacc[nb][1] : -1e30f;
            sacc[nb][2] = mh.x ? sacc[nb][2] : -1e30f;
            sacc[nb][3] = mh.y ? sacc[nb][3] : -1e30f;
            mx_lo = fmaxf(mx_lo, fmaxf(sacc[nb][0], sacc[nb][1]));
            mx_hi = fmaxf(mx_hi, fmaxf(sacc[nb][2], sacc[nb][3]));
        }
        mx_lo = fmaxf(mx_lo, __shfl_xor_sync(0xffffffffu, mx_lo, 1));
        mx_lo = fmaxf(mx_lo, __shfl_xor_sync(0xffffffffu, mx_lo, 2));
        mx_hi = fmaxf(mx_hi, __shfl_xor_sync(0xffffffffu, mx_hi, 1));
        mx_hi = fmaxf(mx_hi, __shfl_xor_sync(0xffffffffu, mx_hi, 2));

        float mn_lo = fmaxf(m_lo, mx_lo);
        float mn_hi = fmaxf(m_hi, mx_hi);
        float corr_lo = __expf(m_lo - mn_lo);
        float corr_hi = __expf(m_hi - mn_hi);
        m_lo = mn_lo; m_hi = mn_hi;

        float s_lo = 0.f, s_hi = 0.f;
        #pragma unroll
        for (int nb = 0; nb < 8; nb++) {
            float p0 = __expf(sacc[nb][0] - mn_lo);
            float p1 = __expf(sacc[nb][1] - mn_lo);
            float p2 = __expf(sacc[nb][2] - mn_hi);
            float p3 = __expf(sacc[nb][3] - mn_hi);
            s_lo += p0 + p1;
            s_hi += p2 + p3;
            sacc[nb][0] = to_tf32(p0);
            sacc[nb][1] = to_tf32(p1);
            sacc[nb][2] = to_tf32(p2);
            sacc[nb][3] = to_tf32(p3);
        }
        s_lo += __shfl_xor_sync(0xffffffffu, s_lo, 1);
        s_lo += __shfl_xor_sync(0xffffffffu, s_lo, 2);
        s_hi += __shfl_xor_sync(0xffffffffu, s_hi, 1);
        s_hi += __shfl_xor_sync(0xffffffffu, s_hi, 2);
        l_lo = l_lo * corr_lo + s_lo;
        l_hi = l_hi * corr_hi + s_hi;

        #pragma unroll
        for (int nb = 0; nb < 8; nb++) {
            oacc[nb][0] *= corr_lo; oacc[nb][1] *= corr_lo;
            oacc[nb][2] *= corr_hi; oacc[nb][3] *= corr_hi;
        }

        // ---- O += P @ V, A-fragments built from sacc via shuffles ----
        // sacc[nb] of lane (g,t') holds P[g][8nb+2t'+j], P[g+8][8nb+2t'+j], j=0/1.
        // Fragment col c = 8ks + t (and +4): owner t' = c>>1 within quad, j = c&1.
        #pragma unroll
        for (int ks = 0; ks < 8; ks++) {
            float v00 = __shfl_sync(0xffffffffu, sacc[ks][0], lane_lo);
            float v01 = __shfl_sync(0xffffffffu, sacc[ks][1], lane_lo);
            float v10 = __shfl_sync(0xffffffffu, sacc[ks][2], lane_lo);
            float v11 = __shfl_sync(0xffffffffu, sacc[ks][3], lane_lo);
            float w00 = __shfl_sync(0xffffffffu, sacc[ks][0], lane_hi);
            float w01 = __shfl_sync(0xffffffffu, sacc[ks][1], lane_hi);
            float w10 = __shfl_sync(0xffffffffu, sacc[ks][2], lane_hi);
            float w11 = __shfl_sync(0xffffffffu, sacc[ks][3], lane_hi);
            uint32_t pa[4];
            pa[0] = __float_as_uint(odd ? v01 : v00);   // P[g][8ks+t]
            pa[1] = __float_as_uint(odd ? v11 : v10);   // P[g+8][8ks+t]
            pa[2] = __float_as_uint(odd ? w01 : w00);   // P[g][8ks+t+4]
            pa[3] = __float_as_uint(odd ? w11 : w10);   // P[g+8][8ks+t+4]
            #pragma unroll
            for (int nb = 0; nb < 8; nb++) {
                const float* Vp = Vs + (ks * 8 + t) * KV_STRIDE + nb * 8 + g;
                mma8(oacc[nb], pa, __float_as_uint(Vp[0]),
                     __float_as_uint(Vp[4 * KV_STRIDE]));
            }
        }
        __syncthreads();   // stage fully consumed before next prefetch refills it
    }

    // ---- normalize, tf32-round, write Hcat ----
    float inv_lo = 1.f / l_lo;
    float inv_hi = 1.f / l_hi;
    float* Crow_lo = g_C + (size_t)(q0 + wrow + g) * (NH * HD) + h * HD;
    float* Crow_hi = Crow_lo + (size_t)8 * (NH * HD);
    #pragma unroll
    for (int nb = 0; nb < 8; nb++) {
        float2 lo = make_float2(to_tf32(oacc[nb][0] * inv_lo), to_tf32(oacc[nb][1] * inv_lo));
        float2 hi = make_float2(to_tf32(oacc[nb][2] * inv_hi), to_tf32(oacc[nb][3] * inv_hi));
        *(float2*)(Crow_lo + nb * 8 + 2 * t) = lo;
        *(float2*)(Crow_hi + nb * 8 + 2 * t) = hi;
    }
}

// ---------------------------------------------------------------------------
// Kernel 3: output projection via mma.sync tf32 (unchanged, measured ~31us)
// ---------------------------------------------------------------------------
__global__ __launch_bounds__(256, 2) void proj_kernel(
    const float* __restrict__ Wo, float* __restrict__ out)
{
    __shared__ float Cs[128][36];
    __shared__ float Ws[128][36];

    const int m0 = blockIdx.x * 128;
    const int n0 = blockIdx.y * 128;
    const int tid  = threadIdx.x;
    const int lane = tid & 31;
    const int g = lane >> 2;
    const int t = lane & 3;
    const int wrow = (tid >> 5) * 16;

    float acc[16][4];
    #pragma unroll
    for (int nb = 0; nb < 16; nb++)
        #pragma unroll
        for (int i = 0; i < 4; i++) acc[nb][i] = 0.f;

    for (int f0 = 0; f0 < FIN; f0 += 32) {
        #pragma unroll
        for (int u = 0; u < 4; u++) {
            int idx = tid + u * 256;
            int r = idx >> 3, c4 = (idx & 7) << 2;
            float4 cv = *(const float4*)(g_C + (size_t)(m0 + r) * (NH * HD) + f0 + c4);
            Cs[r][c4 + 0] = cv.x; Cs[r][c4 + 1] = cv.y;
            Cs[r][c4 + 2] = cv.z; Cs[r][c4 + 3] = cv.w;
            float4 wv = *(const float4*)(Wo + (size_t)(n0 + r) * (NH * HD) + f0 + c4);
            Ws[r][c4 + 0] = to_tf32(wv.x); Ws[r][c4 + 1] = to_tf32(wv.y);
            Ws[r][c4 + 2] = to_tf32(wv.z); Ws[r][c4 + 3] = to_tf32(wv.w);
        }
        __syncthreads();

        uint32_t a[4][4];
        #pragma unroll
        for (int ks = 0; ks < 4; ks++) {
            const float* Cr = &Cs[wrow + g][ks * 8 + t];
            a[ks][0] = __float_as_uint(Cr[0]);
            a[ks][1] = __float_as_uint(Cr[8 * 36]);
            a[ks][2] = __float_as_uint(Cr[4]);
            a[ks][3] = __float_as_uint(Cr[8 * 36 + 4]);
        }
        #pragma unroll
        for (int nb = 0; nb < 16; nb++) {
            #pragma unroll
            for (int ks = 0; ks < 4; ks++) {
                const float* Wp = &Ws[nb * 8 + g][ks * 8 + t];
                mma8(acc[nb], a[ks], __float_as_uint(Wp[0]), __float_as_uint(Wp[4]));
            }
        }
        __syncthreads();
    }

    #pragma unroll
    for (int nb = 0; nb < 16; nb++) {
        size_t r0 = (size_t)(m0 + wrow + g) * FOUT + n0 + nb * 8 + 2 * t;
        *(float2*)(out + r0) = make_float2(acc[nb][0], acc[nb][1]);
        *(float2*)(out + r0 + (size_t)8 * FOUT) = make_float2(acc[nb][2], acc[nb][3]);
    }
}

// ---------------------------------------------------------------------------
extern "C" void kernel_launch(void* const* d_in, const int* in_sizes, int n_in,
                              void* d_out, int out_size)
{
    const float* X    = (const float*)d_in[0];
    const int*   mask = (const int*)  d_in[1];
    const float* Wq   = (const float*)d_in[2];
    const float* Wk   = (const float*)d_in[3];
    const float* Wv   = (const float*)d_in[4];
    const float* Wo   = (const float*)d_in[5];
    float*       out  = (float*)d_out;

    cudaFuncSetAttribute(attn_kernel,
                         cudaFuncAttributeMaxDynamicSharedMemorySize, ATTN_SMEM_BYTES);

    // attn stays at global launch index 5 for ncu (-s 5 -c 1)
    qkv_kernel<<<dim3(NSEQ / 128, NH, 3), 256>>>(X, Wq, Wk, Wv);
    dummy_kernel<<<1, 1>>>();
    dummy_kernel<<<1, 1>>>();
    attn_kernel<<<dim3(NSEQ / QT, NH), 256, ATTN_SMEM_BYTES>>>(mask);
    proj_kernel<<<dim3(NSEQ / 128, FOUT / 128), 256>>>(Wo, out);
}